// round 7
// baseline (speedup 1.0000x reference)
#include <cuda_runtime.h>
#include <cuda_fp16.h>
#include <math.h>
#include <stdint.h>

#define BQ        16384
#define OBJ_FEAT  1024
#define PVF_DIM   1024
#define PPF_DIM   64
#define HIDDEN    512
#define OBJ_NUM   1001
#define PRED_NUM  132

#define OBJ_PAD   1024
#define PRED_PAD  256

// ---------------- scratch (__device__ globals; allocation-free rule) --------
__device__ __half g_sfh[(size_t)BQ * OBJ_FEAT];
__device__ __half g_ofh[(size_t)BQ * OBJ_FEAT];
__device__ __half g_pvfh[(size_t)BQ * PVF_DIM];
__device__ __half g_ppfh[(size_t)BQ * PPF_DIM];
__device__ __half g_Hs[(size_t)BQ * HIDDEN];
__device__ __half g_Ho[(size_t)BQ * HIDDEN];
__device__ __half g_Hv[(size_t)BQ * HIDDEN];
__device__ __half g_Hp[(size_t)BQ * HIDDEN];
__device__ __half g_Wt1[(size_t)HIDDEN * OBJ_FEAT];            // [512][1024]
__device__ __half g_Wtv[(size_t)HIDDEN * PVF_DIM];             // [512][1024]
__device__ __half g_Wtf[(size_t)HIDDEN * (HIDDEN + PPF_DIM)];  // [512][576]
__device__ __half g_Wt2[(size_t)OBJ_PAD * HIDDEN];             // [1024][512]
__device__ __half g_Wtp[(size_t)PRED_PAD * HIDDEN];            // [256][512]

// ---------------- PTX helpers ----------------
__device__ __forceinline__ uint32_t smem_u32(const void* p) {
    uint32_t a;
    asm("{ .reg .u64 t; cvta.to.shared.u64 t, %1; cvt.u32.u64 %0, t; }" : "=r"(a) : "l"(p));
    return a;
}
__device__ __forceinline__ void mma_f16(float* c, const uint32_t* a, const uint32_t* b) {
    asm volatile(
        "mma.sync.aligned.m16n8k16.row.col.f32.f16.f16.f32 "
        "{%0,%1,%2,%3}, {%4,%5,%6,%7}, {%8,%9}, {%0,%1,%2,%3};"
        : "+f"(c[0]), "+f"(c[1]), "+f"(c[2]), "+f"(c[3])
        : "r"(a[0]), "r"(a[1]), "r"(a[2]), "r"(a[3]), "r"(b[0]), "r"(b[1]));
}
#define LDSM_X4(r0, r1, r2, r3, addr) \
    asm volatile("ldmatrix.sync.aligned.m8n8.x4.shared.b16 {%0,%1,%2,%3}, [%4];" \
        : "=r"(r0), "=r"(r1), "=r"(r2), "=r"(r3) : "r"(addr))
__device__ __forceinline__ void cp16cg(uint32_t dst, const void* src) {
    asm volatile("cp.async.cg.shared.global [%0], [%1], 16;" :: "r"(dst), "l"(src));
}
__device__ __forceinline__ void cp16ca(uint32_t dst, const void* src) {
    asm volatile("cp.async.ca.shared.global [%0], [%1], 16;" :: "r"(dst), "l"(src));
}
#define CP_COMMIT() asm volatile("cp.async.commit_group;" ::: "memory")
#define CP_WAIT(n)  asm volatile("cp.async.wait_group %0;" :: "n"(n) : "memory")

// ---------------- smem layout: 3 stages, A/B tiles [128 rows][64+8 halves] --
#define ROWB      144                           // 128B data + 16B pad
#define T_STAGE   (128 * ROWB)                  // 18432 B
#define STAGE_B   (2 * T_STAGE)                 // 36864 B (A then B)
#define NSTAGE    3
#define SMEM_BYTES (NSTAGE * STAGE_B)           // 110592 B

// ---------------- fused prep: conversions (z 0-3) + transposes (z 4-8) -----
__global__ void prep(const float* __restrict__ sf, const float* __restrict__ of,
                     const float* __restrict__ pvf, const float* __restrict__ ppf,
                     __half* __restrict__ sfh, __half* __restrict__ ofh,
                     __half* __restrict__ pvfh, __half* __restrict__ ppfh,
                     const float* __restrict__ W1, const float* __restrict__ Wv,
                     const float* __restrict__ Wf, const float* __restrict__ W2,
                     const float* __restrict__ Wp,
                     __half* __restrict__ Wt1, __half* __restrict__ Wtv,
                     __half* __restrict__ Wtf, __half* __restrict__ Wt2,
                     __half* __restrict__ Wtp)
{
    const int z = blockIdx.z;
    if (z < 4) {
        const float* in = (z == 0) ? sf : (z == 1) ? of : (z == 2) ? pvf : ppf;
        __half* out = (z == 0) ? sfh : (z == 1) ? ofh : (z == 2) ? pvfh : ppfh;
        const int n8 = (z == 3) ? (BQ * PPF_DIM / 8) : (BQ * OBJ_FEAT / 8);
        for (int i = blockIdx.x * blockDim.x + threadIdx.x; i < n8;
             i += gridDim.x * blockDim.x) {
            const float4 a = *reinterpret_cast<const float4*>(in + (size_t)i * 8);
            const float4 b = *reinterpret_cast<const float4*>(in + (size_t)i * 8 + 4);
            __half2 h[4];
            h[0] = __floats2half2_rn(a.x, a.y);
            h[1] = __floats2half2_rn(a.z, a.w);
            h[2] = __floats2half2_rn(b.x, b.y);
            h[3] = __floats2half2_rn(b.z, b.w);
            *reinterpret_cast<uint4*>(out + (size_t)i * 8) = *reinterpret_cast<uint4*>(h);
        }
    } else {
        const float* W; __half* Wt; int K, N, Npad;
        switch (z) {
            case 4: W = W1; Wt = Wt1; K = OBJ_FEAT; N = HIDDEN; Npad = HIDDEN; break;
            case 5: W = Wv; Wt = Wtv; K = PVF_DIM;  N = HIDDEN; Npad = HIDDEN; break;
            case 6: W = Wf; Wt = Wtf; K = HIDDEN + PPF_DIM; N = HIDDEN; Npad = HIDDEN; break;
            case 7: W = W2; Wt = Wt2; K = HIDDEN; N = OBJ_NUM;  Npad = OBJ_PAD; break;
            default: W = Wp; Wt = Wtp; K = HIDDEN; N = PRED_NUM; Npad = PRED_PAD; break;
        }
        __shared__ float t[32][33];
        const int tx5 = threadIdx.x & 31, ty3 = threadIdx.x >> 5;  // (32, 8)
        const int ntx = Npad / 32, nty = (K + 31) / 32;
        for (int tile = blockIdx.x; tile < ntx * nty; tile += gridDim.x) {
            const int bx = (tile % ntx) * 32;   // n
            const int by = (tile / ntx) * 32;   // k
#pragma unroll
            for (int j = 0; j < 32; j += 8) {
                const int y = by + ty3 + j, x = bx + tx5;
                t[ty3 + j][tx5] = (x < N && y < K) ? W[(size_t)y * N + x] : 0.0f;
            }
            __syncthreads();
#pragma unroll
            for (int j = 0; j < 32; j += 8) {
                const int row = bx + ty3 + j, col = by + tx5;
                if (row < Npad && col < K)
                    Wt[(size_t)row * K + col] = __float2half(t[tx5][ty3 + j]);
            }
            __syncthreads();
        }
    }
}

// ---------------- fp16 mma.sync GEMM: 4 warps, warp tile 64x64 -------------
// C[M,N] = epi(A[M,K] @ Bt[N,K]^T), z-fused. CTA tile 128x128, K-chunk 64.
// EPI 0: none | 1: +bias, ReLU | 2: + so2p[gather]*exp(f).  OUTH: C is half.
template <int EPI, bool CONCAT, bool OUTH>
__global__ void __launch_bounds__(128, 2)
mmagemm(const __half* __restrict__ Az0, const __half* __restrict__ Az1,
        const __half* __restrict__ Az2, const __half* __restrict__ A2,
        const __half* __restrict__ Bt01, const __half* __restrict__ Bt2,
        const float* __restrict__ bias01, const float* __restrict__ bias2,
        void* __restrict__ Cz0, void* __restrict__ Cz1, void* __restrict__ Cz2,
        int N, int K,
        const int* __restrict__ gts, const int* __restrict__ gto,
        const float* __restrict__ so2p, const float* __restrict__ sof)
{
    extern __shared__ __align__(16) char smem[];
    const uint32_t sbase = smem_u32(smem);

    const int z = blockIdx.z;
    const __half* A   = (z == 0) ? Az0 : (z == 1) ? Az1 : Az2;
    const __half* Bt  = (z == 2) ? Bt2 : Bt01;
    const float* bias = (z == 2) ? bias2 : bias01;
    void* Cv          = (z == 0) ? Cz0 : (z == 1) ? Cz1 : Cz2;

    const int tid  = threadIdx.x;
    const int wid  = tid >> 5, lane = tid & 31;
    const int grp  = lane >> 2, t4 = lane & 3;
    const int wy   = wid >> 1, wx = wid & 1;      // warp grid 2x2
    const int m0   = blockIdx.y * 128;
    const int n0   = blockIdx.x * 128;
    const int mW   = wy * 64, nW = wx * 64;

    // ldmatrix per-thread base offsets (bytes within tile)
    const uint32_t offA = (uint32_t)(lane & 15) * ROWB + (uint32_t)(lane >> 4) * 16;
    const uint32_t bRow = (uint32_t)((lane & 7) + ((lane >> 4) & 1) * 8);
    const uint32_t offB = bRow * ROWB + (uint32_t)((lane >> 3) & 1) * 16;

    float acc[4][8][4];
#pragma unroll
    for (int i = 0; i < 4; i++)
#pragma unroll
        for (int j = 0; j < 8; j++)
#pragma unroll
            for (int r = 0; r < 4; r++) acc[i][j][r] = 0.0f;

    // -------- async loaders: [128 rows][64 halves], 8 x 16B per thread/tile -
    const int ldRow = tid;                        // 1 thread per row

    auto load_stage = [&](int kc, int s) {
        const uint32_t abase = sbase + s * STAGE_B;
        const uint32_t bbase = abase + T_STAGE;
#pragma unroll
        for (int q = 0; q < 8; q++) {
            const int k = kc + q * 8;
            const uint32_t dst = abase + (uint32_t)ldRow * ROWB + (uint32_t)q * 16;
            const __half* src;
            if (CONCAT)
                src = (k < HIDDEN) ? (A  + (size_t)(m0 + ldRow) * HIDDEN + k)
                                   : (A2 + (size_t)(m0 + ldRow) * PPF_DIM + (k - HIDDEN));
            else
                src = A + (size_t)(m0 + ldRow) * K + k;
            cp16cg(dst, src);
        }
#pragma unroll
        for (int q = 0; q < 8; q++) {
            const uint32_t dst = bbase + (uint32_t)ldRow * ROWB + (uint32_t)q * 16;
            cp16ca(dst, Bt + (size_t)(n0 + ldRow) * K + kc + q * 8);  // weights: L1-cache
        }
    };

    const int NT = K >> 6;                        // K-chunk = 64

    load_stage(0, 0); CP_COMMIT();
    load_stage(64, 1); CP_COMMIT();

    for (int t = 0; t < NT; t++) {
        if (t + 1 < NT) { CP_WAIT(1); } else { CP_WAIT(0); }
        __syncthreads();
        if (t + 2 < NT) { load_stage((t + 2) << 6, (t + 2) % NSTAGE); CP_COMMIT(); }

        const int s = t % NSTAGE;
        const uint32_t abase = sbase + s * STAGE_B;
        const uint32_t bbase = abase + T_STAGE;
#pragma unroll
        for (int ks = 0; ks < 4; ks++) {          // 4 k16-steps per chunk
            const uint32_t kb = (uint32_t)ks * 32;  // 16 halves = 32B
            uint32_t af[4][4], bf[8][2];
#pragma unroll
            for (int i = 0; i < 4; i++) {
                const uint32_t ad = abase + (uint32_t)(mW + i * 16) * ROWB + kb + offA;
                LDSM_X4(af[i][0], af[i][1], af[i][2], af[i][3], ad);
            }
#pragma unroll
            for (int jp = 0; jp < 4; jp++) {
                const uint32_t bd = bbase + (uint32_t)(nW + jp * 16) * ROWB + kb + offB;
                LDSM_X4(bf[2 * jp][0], bf[2 * jp][1], bf[2 * jp + 1][0], bf[2 * jp + 1][1], bd);
            }
#pragma unroll
            for (int i = 0; i < 4; i++)
#pragma unroll
                for (int j = 0; j < 8; j++)
                    mma_f16(acc[i][j], af[i], bf[j]);
        }
    }

    // -------- epilogue --------
    float ef = 0.0f;
    if (EPI == 2) ef = expf(sof[0]);

#pragma unroll
    for (int i = 0; i < 4; i++) {
#pragma unroll
        for (int half = 0; half < 2; half++) {
            const int gm = m0 + mW + i * 16 + grp + half * 8;
            size_t sob = 0;
            if (EPI == 2)
                sob = ((size_t)gts[gm] * OBJ_NUM + (size_t)gto[gm]) * (size_t)PRED_NUM;
#pragma unroll
            for (int j = 0; j < 8; j++) {
                const int gn = n0 + nW + j * 8 + t4 * 2;
                const float v0 = acc[i][j][half * 2 + 0];
                const float v1 = acc[i][j][half * 2 + 1];
                if (OUTH) {
                    __half* crow = (__half*)Cv + (size_t)gm * N;
                    float a0 = v0, a1 = v1;
                    if (EPI == 1) {
                        a0 = fmaxf(a0 + bias[gn], 0.0f);
                        a1 = fmaxf(a1 + bias[gn + 1], 0.0f);
                    }
                    *reinterpret_cast<__half2*>(crow + gn) = __floats2half2_rn(a0, a1);
                } else {
                    float* crow = (float*)Cv + (size_t)gm * N;
                    if (EPI == 2) {
                        if (gn < N)     crow[gn]     = v0 + so2p[sob + gn] * ef;
                        if (gn + 1 < N) crow[gn + 1] = v1 + so2p[sob + gn + 1] * ef;
                    } else {
                        if (gn < N)     crow[gn]     = v0;
                        if (gn + 1 < N) crow[gn + 1] = v1;
                    }
                }
            }
        }
    }
}

// ---------------- host ----------------
extern "C" void kernel_launch(void* const* d_in, const int* in_sizes, int n_in,
                              void* d_out, int out_size)
{
    const float* inp_sf  = (const float*)d_in[0];
    const float* inp_of  = (const float*)d_in[1];
    const float* inp_ppf = (const float*)d_in[2];
    const float* inp_pvf = (const float*)d_in[3];
    const int*   gt_s    = (const int*)d_in[4];
    const int*   gt_o    = (const int*)d_in[5];
    const float* W_obj1  = (const float*)d_in[6];
    const float* b_obj1  = (const float*)d_in[7];
    const float* W_obj2  = (const float*)d_in[8];
    const float* W_pvf   = (const float*)d_in[9];
    const float* b_pvf   = (const float*)d_in[10];
    const float* W_pf    = (const float*)d_in[11];
    const float* b_pf    = (const float*)d_in[12];
    const float* W_pred  = (const float*)d_in[13];
    const float* so2p    = (const float*)d_in[14];
    const float* sof     = (const float*)d_in[15];

    float* out   = (float*)d_out;
    float* out_s = out;
    float* out_o = out + (size_t)BQ * OBJ_NUM;
    float* out_p = out + (size_t)2 * BQ * OBJ_NUM;

    __half *sfh, *ofh, *pvfh, *ppfh, *Hs, *Ho, *Hv, *Hp, *Wt1, *Wtv, *Wtf, *Wt2, *Wtp;
    cudaGetSymbolAddress((void**)&sfh,  g_sfh);
    cudaGetSymbolAddress((void**)&ofh,  g_ofh);
    cudaGetSymbolAddress((void**)&pvfh, g_pvfh);
    cudaGetSymbolAddress((void**)&ppfh, g_ppfh);
    cudaGetSymbolAddress((void**)&Hs,  g_Hs);
    cudaGetSymbolAddress((void**)&Ho,  g_Ho);
    cudaGetSymbolAddress((void**)&Hv,  g_Hv);
    cudaGetSymbolAddress((void**)&Hp,  g_Hp);
    cudaGetSymbolAddress((void**)&Wt1, g_Wt1);
    cudaGetSymbolAddress((void**)&Wtv, g_Wtv);
    cudaGetSymbolAddress((void**)&Wtf, g_Wtf);
    cudaGetSymbolAddress((void**)&Wt2, g_Wt2);
    cudaGetSymbolAddress((void**)&Wtp, g_Wtp);

    cudaFuncSetAttribute(mmagemm<1, false, true>,  cudaFuncAttributeMaxDynamicSharedMemorySize, SMEM_BYTES);
    cudaFuncSetAttribute(mmagemm<1, true,  true>,  cudaFuncAttributeMaxDynamicSharedMemorySize, SMEM_BYTES);
    cudaFuncSetAttribute(mmagemm<0, false, false>, cudaFuncAttributeMaxDynamicSharedMemorySize, SMEM_BYTES);
    cudaFuncSetAttribute(mmagemm<2, false, false>, cudaFuncAttributeMaxDynamicSharedMemorySize, SMEM_BYTES);

    // single fused prep launch (4 conversions + 5 transpose/pad/convert)
    prep<<<dim3(512, 1, 9), 256>>>(inp_sf, inp_of, inp_pvf, inp_ppf,
                                   sfh, ofh, pvfh, ppfh,
                                   W_obj1, W_pvf, W_pf, W_obj2, W_pred,
                                   Wt1, Wtv, Wtf, Wt2, Wtp);

    const dim3 blk(128);

    // stage 1: sf/of/pvf fused over z (K=1024, N=512)
    mmagemm<1, false, true><<<dim3(HIDDEN / 128, BQ / 128, 3), blk, SMEM_BYTES>>>(
        sfh, ofh, pvfh, nullptr, Wt1, Wtv, b_obj1, b_pvf,
        Hs, Ho, Hv, HIDDEN, OBJ_FEAT, nullptr, nullptr, nullptr, nullptr);

    // stage 2: pf_emb (concat Hv | ppf), K = 576
    mmagemm<1, true, true><<<dim3(HIDDEN / 128, BQ / 128, 1), blk, SMEM_BYTES>>>(
        Hv, Hv, Hv, ppfh, Wtf, Wtf, b_pf, b_pf,
        Hp, Hp, Hp, HIDDEN, HIDDEN + PPF_DIM, nullptr, nullptr, nullptr, nullptr);

    // stage 3a: s/o scores fused over z (K=512, N=1001 padded 1024)
    mmagemm<0, false, false><<<dim3(OBJ_PAD / 128, BQ / 128, 2), blk, SMEM_BYTES>>>(
        Hs, Ho, Ho, nullptr, Wt2, Wt2, nullptr, nullptr,
        out_s, out_o, out_o, OBJ_NUM, HIDDEN, nullptr, nullptr, nullptr, nullptr);

    // stage 3b: predicate scores + so2p gather (K=512, N=132 padded 256)
    mmagemm<2, false, false><<<dim3(PRED_PAD / 128, BQ / 128, 1), blk, SMEM_BYTES>>>(
        Hp, Hp, Hp, nullptr, Wtp, Wtp, nullptr, nullptr,
        out_p, out_p, out_p, PRED_NUM, HIDDEN, gt_s, gt_o, so2p, sof);
}

// round 8
// speedup vs baseline: 1.1107x; 1.1107x over previous
#include <cuda_runtime.h>
#include <cuda_fp16.h>
#include <math.h>
#include <stdint.h>

#define BQ        16384
#define OBJ_FEAT  1024
#define PVF_DIM   1024
#define PPF_DIM   64
#define HIDDEN    512
#define OBJ_NUM   1001
#define PRED_NUM  132

#define OBJ_PAD   1024
#define PRED_PAD  256

// ---------------- scratch (__device__ globals; allocation-free rule) --------
__device__ __half g_sfh[(size_t)BQ * OBJ_FEAT];
__device__ __half g_ofh[(size_t)BQ * OBJ_FEAT];
__device__ __half g_pvfh[(size_t)BQ * PVF_DIM];
__device__ __half g_ppfh[(size_t)BQ * PPF_DIM];
__device__ __half g_Hs[(size_t)BQ * HIDDEN];
__device__ __half g_Ho[(size_t)BQ * HIDDEN];
__device__ __half g_Hv[(size_t)BQ * HIDDEN];
__device__ __half g_Hp[(size_t)BQ * HIDDEN];
__device__ __half g_Wt1[(size_t)HIDDEN * OBJ_FEAT];            // [512][1024]
__device__ __half g_Wtv[(size_t)HIDDEN * PVF_DIM];             // [512][1024]
__device__ __half g_Wtf[(size_t)HIDDEN * (HIDDEN + PPF_DIM)];  // [512][576]
__device__ __half g_Wt2[(size_t)OBJ_PAD * HIDDEN];             // [1024][512]
__device__ __half g_Wtp[(size_t)PRED_PAD * HIDDEN];            // [256][512]

// ---------------- PTX helpers ----------------
__device__ __forceinline__ uint32_t smem_u32(const void* p) {
    uint32_t a;
    asm("{ .reg .u64 t; cvta.to.shared.u64 t, %1; cvt.u32.u64 %0, t; }" : "=r"(a) : "l"(p));
    return a;
}
__device__ __forceinline__ void mma_f16(float* c, const uint32_t* a, const uint32_t* b) {
    asm volatile(
        "mma.sync.aligned.m16n8k16.row.col.f32.f16.f16.f32 "
        "{%0,%1,%2,%3}, {%4,%5,%6,%7}, {%8,%9}, {%0,%1,%2,%3};"
        : "+f"(c[0]), "+f"(c[1]), "+f"(c[2]), "+f"(c[3])
        : "r"(a[0]), "r"(a[1]), "r"(a[2]), "r"(a[3]), "r"(b[0]), "r"(b[1]));
}
#define LDSM_X4(r0, r1, r2, r3, addr) \
    asm volatile("ldmatrix.sync.aligned.m8n8.x4.shared.b16 {%0,%1,%2,%3}, [%4];" \
        : "=r"(r0), "=r"(r1), "=r"(r2), "=r"(r3) : "r"(addr))
__device__ __forceinline__ void cp16cg(uint32_t dst, const void* src) {
    asm volatile("cp.async.cg.shared.global [%0], [%1], 16;" :: "r"(dst), "l"(src));
}
__device__ __forceinline__ void cp16ca(uint32_t dst, const void* src) {
    asm volatile("cp.async.ca.shared.global [%0], [%1], 16;" :: "r"(dst), "l"(src));
}
#define CP_COMMIT() asm volatile("cp.async.commit_group;" ::: "memory")
#define CP_WAIT(n)  asm volatile("cp.async.wait_group %0;" :: "n"(n) : "memory")

// ---------------- smem: 3 stages, A [256 rows], B [128 rows], 64 halves ----
#define ROWB      144                           // 128B data + 16B pad
#define A_STAGE   (256 * ROWB)                  // 36864 B
#define B_STAGE   (128 * ROWB)                  // 18432 B
#define STAGE_B   (A_STAGE + B_STAGE)           // 55296 B
#define NSTAGE    3
#define SMEM_BYTES (NSTAGE * STAGE_B)           // 165888 B

// ---------------- fused prep: conversions (z 0-3) + transposes (z 4-8) -----
__global__ void prep(const float* __restrict__ sf, const float* __restrict__ of,
                     const float* __restrict__ pvf, const float* __restrict__ ppf,
                     __half* __restrict__ sfh, __half* __restrict__ ofh,
                     __half* __restrict__ pvfh, __half* __restrict__ ppfh,
                     const float* __restrict__ W1, const float* __restrict__ Wv,
                     const float* __restrict__ Wf, const float* __restrict__ W2,
                     const float* __restrict__ Wp,
                     __half* __restrict__ Wt1, __half* __restrict__ Wtv,
                     __half* __restrict__ Wtf, __half* __restrict__ Wt2,
                     __half* __restrict__ Wtp)
{
    const int z = blockIdx.z;
    if (z < 4) {
        const float* in = (z == 0) ? sf : (z == 1) ? of : (z == 2) ? pvf : ppf;
        __half* out = (z == 0) ? sfh : (z == 1) ? ofh : (z == 2) ? pvfh : ppfh;
        const int n8 = (z == 3) ? (BQ * PPF_DIM / 8) : (BQ * OBJ_FEAT / 8);
        for (int i = blockIdx.x * blockDim.x + threadIdx.x; i < n8;
             i += gridDim.x * blockDim.x) {
            const float4 a = *reinterpret_cast<const float4*>(in + (size_t)i * 8);
            const float4 b = *reinterpret_cast<const float4*>(in + (size_t)i * 8 + 4);
            __half2 h[4];
            h[0] = __floats2half2_rn(a.x, a.y);
            h[1] = __floats2half2_rn(a.z, a.w);
            h[2] = __floats2half2_rn(b.x, b.y);
            h[3] = __floats2half2_rn(b.z, b.w);
            *reinterpret_cast<uint4*>(out + (size_t)i * 8) = *reinterpret_cast<uint4*>(h);
        }
    } else {
        const float* W; __half* Wt; int K, N, Npad;
        switch (z) {
            case 4: W = W1; Wt = Wt1; K = OBJ_FEAT; N = HIDDEN; Npad = HIDDEN; break;
            case 5: W = Wv; Wt = Wtv; K = PVF_DIM;  N = HIDDEN; Npad = HIDDEN; break;
            case 6: W = Wf; Wt = Wtf; K = HIDDEN + PPF_DIM; N = HIDDEN; Npad = HIDDEN; break;
            case 7: W = W2; Wt = Wt2; K = HIDDEN; N = OBJ_NUM;  Npad = OBJ_PAD; break;
            default: W = Wp; Wt = Wtp; K = HIDDEN; N = PRED_NUM; Npad = PRED_PAD; break;
        }
        __shared__ float t[32][33];
        const int tx5 = threadIdx.x & 31, ty3 = threadIdx.x >> 5;  // (32, 8)
        const int ntx = Npad / 32, nty = (K + 31) / 32;
        for (int tile = blockIdx.x; tile < ntx * nty; tile += gridDim.x) {
            const int bx = (tile % ntx) * 32;   // n
            const int by = (tile / ntx) * 32;   // k
#pragma unroll
            for (int j = 0; j < 32; j += 8) {
                const int y = by + ty3 + j, x = bx + tx5;
                t[ty3 + j][tx5] = (x < N && y < K) ? W[(size_t)y * N + x] : 0.0f;
            }
            __syncthreads();
#pragma unroll
            for (int j = 0; j < 32; j += 8) {
                const int row = bx + ty3 + j, col = by + tx5;
                if (row < Npad && col < K)
                    Wt[(size_t)row * K + col] = __float2half(t[tx5][ty3 + j]);
            }
            __syncthreads();
        }
    }
}

// ---------------- fp16 mma.sync GEMM: CTA 256x128, 8 warps 4x2... ----------
// 16 warps? No: 256 threads = 8 warps. Warp grid 4(m) x 2(n), warp tile 64x64?
// -> We use 256 threads = 8 warps, warp grid 4x2, warp tile 64x64 would blow
//    regs. Instead: warp tile 64x32 requires 16 warps for 256x128.
//    So blockDim = 512? No: keep 256 threads, warp grid 4x2, warp tile 64x64
//    is reg-heavy. Choose: 512 threads (16 warps) warp tile 64x32.
// Final: 512 threads, 16 warps, warp grid 4(m) x 4(n), warp tile 64x32.
// EPI 0: none | 1: +bias, ReLU | 3: z<2 plain, z==2 so2p.  OUTH: C is half.
template <int EPI, bool CONCAT, bool OUTH>
__global__ void __launch_bounds__(512, 1)
mmagemm(const __half* __restrict__ Az0, const __half* __restrict__ Az1,
        const __half* __restrict__ Az2, const __half* __restrict__ A2,
        const __half* __restrict__ Bt01, const __half* __restrict__ Bt2,
        const float* __restrict__ bias01, const float* __restrict__ bias2,
        void* __restrict__ Cz0, void* __restrict__ Cz1, void* __restrict__ Cz2,
        int N01, int N2, int K,
        const int* __restrict__ gts, const int* __restrict__ gto,
        const float* __restrict__ so2p, const float* __restrict__ sof)
{
    const int z = blockIdx.z;
    const bool isP = (EPI == 3) && (z == 2);
    if (isP && blockIdx.x >= 2) return;           // pred uses only 2 n-tiles

    extern __shared__ __align__(16) char smem[];
    const uint32_t sbase = smem_u32(smem);

    const __half* A   = (z == 0) ? Az0 : (z == 1) ? Az1 : Az2;
    const __half* Bt  = (z == 2) ? Bt2 : Bt01;
    const float* bias = (z == 2) ? bias2 : bias01;
    void* Cv          = (z == 0) ? Cz0 : (z == 1) ? Cz1 : Cz2;
    const int N       = isP ? N2 : N01;

    const int tid  = threadIdx.x;
    const int wid  = tid >> 5, lane = tid & 31;
    const int grp  = lane >> 2, t4 = lane & 3;
    const int wy   = wid >> 2, wx = wid & 3;      // warp grid 4x4
    const int m0   = blockIdx.y * 256;
    const int n0   = blockIdx.x * 128;
    const int mW   = wy * 64, nW = wx * 32;

    // ldmatrix per-thread base offsets (bytes within tile)
    const uint32_t offA = (uint32_t)(lane & 15) * ROWB + (uint32_t)(lane >> 4) * 16;
    const uint32_t bRow = (uint32_t)((lane & 7) + ((lane >> 4) & 1) * 8);
    const uint32_t offB = bRow * ROWB + (uint32_t)((lane >> 3) & 1) * 16;

    float acc[4][4][4];
#pragma unroll
    for (int i = 0; i < 4; i++)
#pragma unroll
        for (int j = 0; j < 4; j++)
#pragma unroll
            for (int r = 0; r < 4; r++) acc[i][j][r] = 0.0f;

    // -------- async loaders: A 256 rows, B 128 rows, 64 halves per row -----
    // 512 threads: A: 2 threads/row, 4 x 16B each; B: 4 threads/row, 2 x 16B.
    const int aRow = tid >> 1, aQ0 = (tid & 1) * 4;
    const int bRowLd = tid >> 2, bQ0 = (tid & 3) * 2;

    auto load_stage = [&](int kc, int s) {
        const uint32_t abase = sbase + s * STAGE_B;
        const uint32_t bbase = abase + A_STAGE;
#pragma unroll
        for (int i = 0; i < 4; i++) {
            const int q = aQ0 + i;
            const int k = kc + q * 8;
            const uint32_t dst = abase + (uint32_t)aRow * ROWB + (uint32_t)q * 16;
            const __half* src;
            if (CONCAT)
                src = (k < HIDDEN) ? (A  + (size_t)(m0 + aRow) * HIDDEN + k)
                                   : (A2 + (size_t)(m0 + aRow) * PPF_DIM + (k - HIDDEN));
            else
                src = A + (size_t)(m0 + aRow) * K + k;
            cp16cg(dst, src);
        }
#pragma unroll
        for (int i = 0; i < 2; i++) {
            const int q = bQ0 + i;
            const uint32_t dst = bbase + (uint32_t)bRowLd * ROWB + (uint32_t)q * 16;
            cp16ca(dst, Bt + (size_t)(n0 + bRowLd) * K + kc + q * 8);
        }
    };

    const int NT = K >> 6;                        // K-chunk = 64

    load_stage(0, 0); CP_COMMIT();
    load_stage(64, 1); CP_COMMIT();

    uint32_t afb[2][4][4], bfb[2][4][2];

    auto ldsm_step = [&](uint32_t abase, uint32_t bbase, int ks, int buf) {
        const uint32_t kb = (uint32_t)ks * 32;
#pragma unroll
        for (int i = 0; i < 4; i++) {
            const uint32_t ad = abase + (uint32_t)(mW + i * 16) * ROWB + kb + offA;
            LDSM_X4(afb[buf][i][0], afb[buf][i][1], afb[buf][i][2], afb[buf][i][3], ad);
        }
#pragma unroll
        for (int jp = 0; jp < 2; jp++) {
            const uint32_t bd = bbase + (uint32_t)(nW + jp * 16) * ROWB + kb + offB;
            LDSM_X4(bfb[buf][2 * jp][0], bfb[buf][2 * jp][1],
                    bfb[buf][2 * jp + 1][0], bfb[buf][2 * jp + 1][1], bd);
        }
    };

    for (int t = 0; t < NT; t++) {
        if (t + 1 < NT) { CP_WAIT(1); } else { CP_WAIT(0); }
        __syncthreads();
        if (t + 2 < NT) { load_stage((t + 2) << 6, (t + 2) % NSTAGE); }
        CP_COMMIT();

        const int s = t % NSTAGE;
        const uint32_t abase = sbase + s * STAGE_B;
        const uint32_t bbase = abase + A_STAGE;

        ldsm_step(abase, bbase, 0, 0);
#pragma unroll
        for (int ks = 0; ks < 4; ks++) {          // 4 k16-steps, frag dbl-buf
            const int cur = ks & 1;
            if (ks < 3) ldsm_step(abase, bbase, ks + 1, cur ^ 1);
#pragma unroll
            for (int i = 0; i < 4; i++)
#pragma unroll
                for (int j = 0; j < 4; j++)
                    mma_f16(acc[i][j], afb[cur][i], bfb[cur][j]);
        }
    }

    // -------- epilogue --------
    float ef = 0.0f;
    if (EPI == 3) ef = expf(sof[0]);              // only used when isP

#pragma unroll
    for (int i = 0; i < 4; i++) {
#pragma unroll
        for (int half = 0; half < 2; half++) {
            const int gm = m0 + mW + i * 16 + grp + half * 8;
            size_t sob = 0;
            if (EPI == 3) {
                if (isP)
                    sob = ((size_t)gts[gm] * OBJ_NUM + (size_t)gto[gm]) * (size_t)PRED_NUM;
            }
#pragma unroll
            for (int j = 0; j < 4; j++) {
                const int gn = n0 + nW + j * 8 + t4 * 2;
                const float v0 = acc[i][j][half * 2 + 0];
                const float v1 = acc[i][j][half * 2 + 1];
                if (OUTH) {
                    __half* crow = (__half*)Cv + (size_t)gm * N;
                    float a0 = v0, a1 = v1;
                    if (EPI == 1) {
                        a0 = fmaxf(a0 + bias[gn], 0.0f);
                        a1 = fmaxf(a1 + bias[gn + 1], 0.0f);
                    }
                    *reinterpret_cast<__half2*>(crow + gn) = __floats2half2_rn(a0, a1);
                } else {
                    float* crow = (float*)Cv + (size_t)gm * N;
                    if (isP) {
                        if (gn < N)     crow[gn]     = v0 + so2p[sob + gn] * ef;
                        if (gn + 1 < N) crow[gn + 1] = v1 + so2p[sob + gn + 1] * ef;
                    } else {
                        if (gn < N)     crow[gn]     = v0;
                        if (gn + 1 < N) crow[gn + 1] = v1;
                    }
                }
            }
        }
    }
}

// ---------------- host ----------------
extern "C" void kernel_launch(void* const* d_in, const int* in_sizes, int n_in,
                              void* d_out, int out_size)
{
    const float* inp_sf  = (const float*)d_in[0];
    const float* inp_of  = (const float*)d_in[1];
    const float* inp_ppf = (const float*)d_in[2];
    const float* inp_pvf = (const float*)d_in[3];
    const int*   gt_s    = (const int*)d_in[4];
    const int*   gt_o    = (const int*)d_in[5];
    const float* W_obj1  = (const float*)d_in[6];
    const float* b_obj1  = (const float*)d_in[7];
    const float* W_obj2  = (const float*)d_in[8];
    const float* W_pvf   = (const float*)d_in[9];
    const float* b_pvf   = (const float*)d_in[10];
    const float* W_pf    = (const float*)d_in[11];
    const float* b_pf    = (const float*)d_in[12];
    const float* W_pred  = (const float*)d_in[13];
    const float* so2p    = (const float*)d_in[14];
    const float* sof     = (const float*)d_in[15];

    float* out   = (float*)d_out;
    float* out_s = out;
    float* out_o = out + (size_t)BQ * OBJ_NUM;
    float* out_p = out + (size_t)2 * BQ * OBJ_NUM;

    __half *sfh, *ofh, *pvfh, *ppfh, *Hs, *Ho, *Hv, *Hp, *Wt1, *Wtv, *Wtf, *Wt2, *Wtp;
    cudaGetSymbolAddress((void**)&sfh,  g_sfh);
    cudaGetSymbolAddress((void**)&ofh,  g_ofh);
    cudaGetSymbolAddress((void**)&pvfh, g_pvfh);
    cudaGetSymbolAddress((void**)&ppfh, g_ppfh);
    cudaGetSymbolAddress((void**)&Hs,  g_Hs);
    cudaGetSymbolAddress((void**)&Ho,  g_Ho);
    cudaGetSymbolAddress((void**)&Hv,  g_Hv);
    cudaGetSymbolAddress((void**)&Hp,  g_Hp);
    cudaGetSymbolAddress((void**)&Wt1, g_Wt1);
    cudaGetSymbolAddress((void**)&Wtv, g_Wtv);
    cudaGetSymbolAddress((void**)&Wtf, g_Wtf);
    cudaGetSymbolAddress((void**)&Wt2, g_Wt2);
    cudaGetSymbolAddress((void**)&Wtp, g_Wtp);

    cudaFuncSetAttribute(mmagemm<1, false, true>,  cudaFuncAttributeMaxDynamicSharedMemorySize, SMEM_BYTES);
    cudaFuncSetAttribute(mmagemm<1, true,  true>,  cudaFuncAttributeMaxDynamicSharedMemorySize, SMEM_BYTES);
    cudaFuncSetAttribute(mmagemm<3, false, false>, cudaFuncAttributeMaxDynamicSharedMemorySize, SMEM_BYTES);

    // single fused prep launch (4 conversions + 5 transpose/pad/convert)
    prep<<<dim3(512, 1, 9), 256>>>(inp_sf, inp_of, inp_pvf, inp_ppf,
                                   sfh, ofh, pvfh, ppfh,
                                   W_obj1, W_pvf, W_pf, W_obj2, W_pred,
                                   Wt1, Wtv, Wtf, Wt2, Wtp);

    const dim3 blk(512);

    // stage 1: sf/of/pvf fused over z (K=1024, N=512), CTA tile 256x128
    mmagemm<1, false, true><<<dim3(HIDDEN / 128, BQ / 256, 3), blk, SMEM_BYTES>>>(
        sfh, ofh, pvfh, nullptr, Wt1, Wtv, b_obj1, b_pvf,
        Hs, Ho, Hv, HIDDEN, HIDDEN, OBJ_FEAT, nullptr, nullptr, nullptr, nullptr);

    // stage 2: pf_emb (concat Hv | ppf), K = 576
    mmagemm<1, true, true><<<dim3(HIDDEN / 128, BQ / 256, 1), blk, SMEM_BYTES>>>(
        Hv, Hv, Hv, ppfh, Wtf, Wtf, b_pf, b_pf,
        Hp, Hp, Hp, HIDDEN, HIDDEN, HIDDEN + PPF_DIM, nullptr, nullptr, nullptr, nullptr);

    // stage 3 merged: z 0/1 = s/o scores (N=1001, 8 n-tiles); z=2 = predicate
    // (N=132, 2 n-tiles, so2p gather). Excess z=2 CTAs exit early.
    mmagemm<3, false, false><<<dim3(OBJ_PAD / 128, BQ / 256, 3), blk, SMEM_BYTES>>>(
        Hs, Ho, Hp, nullptr, Wt2, Wtp, nullptr, nullptr,
        out_s, out_o, out_p, OBJ_NUM, PRED_NUM, HIDDEN, gt_s, gt_o, so2p, sof);
}

// round 9
// speedup vs baseline: 1.2087x; 1.0883x over previous
#include <cuda_runtime.h>
#include <cuda_fp16.h>
#include <math.h>
#include <stdint.h>

#define BQ        16384
#define OBJ_FEAT  1024
#define PVF_DIM   1024
#define PPF_DIM   64
#define HIDDEN    512
#define OBJ_NUM   1001
#define PRED_NUM  132

#define OBJ_PAD   1024
#define PRED_PAD  256

// ---------------- scratch (__device__ globals; allocation-free rule) --------
__device__ __half g_sfh[(size_t)BQ * OBJ_FEAT];
__device__ __half g_ofh[(size_t)BQ * OBJ_FEAT];
__device__ __half g_pvfh[(size_t)BQ * PVF_DIM];
__device__ __half g_ppfh[(size_t)BQ * PPF_DIM];
__device__ __half g_Hs[(size_t)BQ * HIDDEN];
__device__ __half g_Ho[(size_t)BQ * HIDDEN];
__device__ __half g_Hv[(size_t)BQ * HIDDEN];
__device__ __half g_Hp[(size_t)BQ * HIDDEN];
__device__ __half g_Wt1[(size_t)HIDDEN * OBJ_FEAT];            // [512][1024]
__device__ __half g_Wtv[(size_t)HIDDEN * PVF_DIM];             // [512][1024]
__device__ __half g_Wtf[(size_t)HIDDEN * (HIDDEN + PPF_DIM)];  // [512][576]
__device__ __half g_Wt2[(size_t)OBJ_PAD * HIDDEN];             // [1024][512]
__device__ __half g_Wtp[(size_t)PRED_PAD * HIDDEN];            // [256][512]

// ---------------- PTX helpers ----------------
__device__ __forceinline__ uint32_t smem_u32(const void* p) {
    uint32_t a;
    asm("{ .reg .u64 t; cvta.to.shared.u64 t, %1; cvt.u32.u64 %0, t; }" : "=r"(a) : "l"(p));
    return a;
}
__device__ __forceinline__ void mma_f16(float* c, const uint32_t* a, const uint32_t* b) {
    asm volatile(
        "mma.sync.aligned.m16n8k16.row.col.f32.f16.f16.f32 "
        "{%0,%1,%2,%3}, {%4,%5,%6,%7}, {%8,%9}, {%0,%1,%2,%3};"
        : "+f"(c[0]), "+f"(c[1]), "+f"(c[2]), "+f"(c[3])
        : "r"(a[0]), "r"(a[1]), "r"(a[2]), "r"(a[3]), "r"(b[0]), "r"(b[1]));
}
#define LDSM_X4(r0, r1, r2, r3, addr) \
    asm volatile("ldmatrix.sync.aligned.m8n8.x4.shared.b16 {%0,%1,%2,%3}, [%4];" \
        : "=r"(r0), "=r"(r1), "=r"(r2), "=r"(r3) : "r"(addr))
__device__ __forceinline__ void cp16cg(uint32_t dst, const void* src) {
    asm volatile("cp.async.cg.shared.global [%0], [%1], 16;" :: "r"(dst), "l"(src));
}
__device__ __forceinline__ void cp16ca(uint32_t dst, const void* src) {
    asm volatile("cp.async.ca.shared.global [%0], [%1], 16;" :: "r"(dst), "l"(src));
}
#define CP_COMMIT() asm volatile("cp.async.commit_group;" ::: "memory")
#define CP_WAIT(n)  asm volatile("cp.async.wait_group %0;" :: "n"(n) : "memory")

// ---------------- smem layout: 3 stages, A/B tiles [128 rows][64+8 halves] --
#define ROWB      144                           // 128B data + 16B pad
#define T_STAGE   (128 * ROWB)                  // 18432 B
#define STAGE_B   (2 * T_STAGE)                 // 36864 B (A then B)
#define NSTAGE    3
#define SMEM_BYTES (NSTAGE * STAGE_B)           // 110592 B

// ---------------- fused prep: conversions (z 0-3) + transposes (z 4-8) -----
__global__ void prep(const float* __restrict__ sf, const float* __restrict__ of,
                     const float* __restrict__ pvf, const float* __restrict__ ppf,
                     __half* __restrict__ sfh, __half* __restrict__ ofh,
                     __half* __restrict__ pvfh, __half* __restrict__ ppfh,
                     const float* __restrict__ W1, const float* __restrict__ Wv,
                     const float* __restrict__ Wf, const float* __restrict__ W2,
                     const float* __restrict__ Wp,
                     __half* __restrict__ Wt1, __half* __restrict__ Wtv,
                     __half* __restrict__ Wtf, __half* __restrict__ Wt2,
                     __half* __restrict__ Wtp)
{
    const int z = blockIdx.z;
    if (z < 4) {
        const float* in = (z == 0) ? sf : (z == 1) ? of : (z == 2) ? pvf : ppf;
        __half* out = (z == 0) ? sfh : (z == 1) ? ofh : (z == 2) ? pvfh : ppfh;
        const int n8 = (z == 3) ? (BQ * PPF_DIM / 8) : (BQ * OBJ_FEAT / 8);
        for (int i = blockIdx.x * blockDim.x + threadIdx.x; i < n8;
             i += gridDim.x * blockDim.x) {
            const float4 a = *reinterpret_cast<const float4*>(in + (size_t)i * 8);
            const float4 b = *reinterpret_cast<const float4*>(in + (size_t)i * 8 + 4);
            __half2 h[4];
            h[0] = __floats2half2_rn(a.x, a.y);
            h[1] = __floats2half2_rn(a.z, a.w);
            h[2] = __floats2half2_rn(b.x, b.y);
            h[3] = __floats2half2_rn(b.z, b.w);
            *reinterpret_cast<uint4*>(out + (size_t)i * 8) = *reinterpret_cast<uint4*>(h);
        }
    } else {
        const float* W; __half* Wt; int K, N, Npad;
        switch (z) {
            case 4: W = W1; Wt = Wt1; K = OBJ_FEAT; N = HIDDEN; Npad = HIDDEN; break;
            case 5: W = Wv; Wt = Wtv; K = PVF_DIM;  N = HIDDEN; Npad = HIDDEN; break;
            case 6: W = Wf; Wt = Wtf; K = HIDDEN + PPF_DIM; N = HIDDEN; Npad = HIDDEN; break;
            case 7: W = W2; Wt = Wt2; K = HIDDEN; N = OBJ_NUM;  Npad = OBJ_PAD; break;
            default: W = Wp; Wt = Wtp; K = HIDDEN; N = PRED_NUM; Npad = PRED_PAD; break;
        }
        __shared__ float t[32][33];
        const int tx5 = threadIdx.x & 31, ty3 = threadIdx.x >> 5;  // (32, 8)
        const int ntx = Npad / 32, nty = (K + 31) / 32;
        for (int tile = blockIdx.x; tile < ntx * nty; tile += gridDim.x) {
            const int bx = (tile % ntx) * 32;   // n
            const int by = (tile / ntx) * 32;   // k
#pragma unroll
            for (int j = 0; j < 32; j += 8) {
                const int y = by + ty3 + j, x = bx + tx5;
                t[ty3 + j][tx5] = (x < N && y < K) ? W[(size_t)y * N + x] : 0.0f;
            }
            __syncthreads();
#pragma unroll
            for (int j = 0; j < 32; j += 8) {
                const int row = bx + ty3 + j, col = by + tx5;
                if (row < Npad && col < K)
                    Wt[(size_t)row * K + col] = __float2half(t[tx5][ty3 + j]);
            }
            __syncthreads();
        }
    }
}

// ================= round-6 champion GEMM core (unchanged) ==================
// 256 threads, 8 warps 2x4, warp tile 64x32, CTA 128x128, K-chunk 64, 3-stage.

struct GemmCore {
    uint32_t sbase;
    int tid, wid, lane, grp, t4, mW, nW;
    uint32_t offA, offB;
    int ldRow, ldQ0;

    __device__ __forceinline__ void init(uint32_t sb) {
        sbase = sb;
        tid = threadIdx.x;
        wid = tid >> 5; lane = tid & 31;
        grp = lane >> 2; t4 = lane & 3;
        const int wy = wid >> 2, wx = wid & 3;     // warp grid 2x4
        mW = wy * 64; nW = wx * 32;
        offA = (uint32_t)(lane & 15) * ROWB + (uint32_t)(lane >> 4) * 16;
        const uint32_t bR = (uint32_t)((lane & 7) + ((lane >> 4) & 1) * 8);
        offB = bR * ROWB + (uint32_t)((lane >> 3) & 1) * 16;
        ldRow = tid >> 1;
        ldQ0 = (tid & 1) * 4;
    }

    // A from concat(Arow-major stride HIDDEN | A2 stride PPF_DIM); for K<=512
    // inputs the A2 branch is never taken.
    __device__ __forceinline__ void load_stage(const __half* __restrict__ A,
                                               const __half* __restrict__ A2,
                                               const __half* __restrict__ Bt,
                                               int m0, int n0, int K,
                                               int kc, int s) const {
        const uint32_t abase = sbase + s * STAGE_B;
        const uint32_t bbase = abase + T_STAGE;
#pragma unroll
        for (int i = 0; i < 4; i++) {
            const int q = ldQ0 + i;
            const int k = kc + q * 8;
            const uint32_t dst = abase + (uint32_t)ldRow * ROWB + (uint32_t)q * 16;
            const __half* src = (k < HIDDEN)
                ? (A  + (size_t)(m0 + ldRow) * HIDDEN + k)
                : (A2 + (size_t)(m0 + ldRow) * PPF_DIM + (k - HIDDEN));
            cp16cg(dst, src);
        }
#pragma unroll
        for (int i = 0; i < 4; i++) {
            const int q = ldQ0 + i;
            const uint32_t dst = bbase + (uint32_t)ldRow * ROWB + (uint32_t)q * 16;
            cp16ca(dst, Bt + (size_t)(n0 + ldRow) * K + kc + q * 8);
        }
    }

    // plain A (row stride == K)
    __device__ __forceinline__ void load_stageP(const __half* __restrict__ A,
                                                const __half* __restrict__ Bt,
                                                int m0, int n0, int K,
                                                int kc, int s) const {
        const uint32_t abase = sbase + s * STAGE_B;
        const uint32_t bbase = abase + T_STAGE;
#pragma unroll
        for (int i = 0; i < 4; i++) {
            const int q = ldQ0 + i;
            const uint32_t dst = abase + (uint32_t)ldRow * ROWB + (uint32_t)q * 16;
            cp16cg(dst, A + (size_t)(m0 + ldRow) * K + kc + q * 8);
        }
#pragma unroll
        for (int i = 0; i < 4; i++) {
            const int q = ldQ0 + i;
            const uint32_t dst = bbase + (uint32_t)ldRow * ROWB + (uint32_t)q * 16;
            cp16ca(dst, Bt + (size_t)(n0 + ldRow) * K + kc + q * 8);
        }
    }

    __device__ __forceinline__ void chunk_mma(int s, float acc[4][4][4]) const {
        const uint32_t abase = sbase + s * STAGE_B;
        const uint32_t bbase = abase + T_STAGE;
#pragma unroll
        for (int ks = 0; ks < 4; ks++) {
            const uint32_t kb = (uint32_t)ks * 32;
            uint32_t af[4][4], bf[4][2];
#pragma unroll
            for (int i = 0; i < 4; i++) {
                const uint32_t ad = abase + (uint32_t)(mW + i * 16) * ROWB + kb + offA;
                LDSM_X4(af[i][0], af[i][1], af[i][2], af[i][3], ad);
            }
#pragma unroll
            for (int jp = 0; jp < 2; jp++) {
                const uint32_t bd = bbase + (uint32_t)(nW + jp * 16) * ROWB + kb + offB;
                LDSM_X4(bf[2 * jp][0], bf[2 * jp][1], bf[2 * jp + 1][0], bf[2 * jp + 1][1], bd);
            }
#pragma unroll
            for (int i = 0; i < 4; i++)
#pragma unroll
                for (int j = 0; j < 4; j++)
                    mma_f16(acc[i][j], af[i], bf[j]);
        }
    }
};

#define ACC_INIT(acc) \
    _Pragma("unroll") for (int i = 0; i < 4; i++) \
    _Pragma("unroll") for (int j = 0; j < 4; j++) \
    _Pragma("unroll") for (int r = 0; r < 4; r++) acc[i][j][r] = 0.0f;

// ---------------- stage 1: 3 hidden GEMMs, bias+ReLU, half out -------------
__global__ void __launch_bounds__(256, 2)
gemm_s1(const __half* __restrict__ Az0, const __half* __restrict__ Az1,
        const __half* __restrict__ Az2,
        const __half* __restrict__ Bt01, const __half* __restrict__ Bt2,
        const float* __restrict__ bias01, const float* __restrict__ bias2,
        __half* __restrict__ Cz0, __half* __restrict__ Cz1, __half* __restrict__ Cz2)
{
    extern __shared__ __align__(16) char smem[];
    GemmCore g; g.init(smem_u32(smem));

    const int z = blockIdx.z;
    const __half* A   = (z == 0) ? Az0 : (z == 1) ? Az1 : Az2;
    const __half* Bt  = (z == 2) ? Bt2 : Bt01;
    const float* bias = (z == 2) ? bias2 : bias01;
    __half* C         = (z == 0) ? Cz0 : (z == 1) ? Cz1 : Cz2;

    const int m0 = blockIdx.y * 128, n0 = blockIdx.x * 128;
    const int K = OBJ_FEAT, NT = K >> 6;

    float acc[4][4][4];
    ACC_INIT(acc);

    g.load_stageP(A, Bt, m0, n0, K, 0, 0); CP_COMMIT();
    g.load_stageP(A, Bt, m0, n0, K, 64, 1); CP_COMMIT();
    for (int t = 0; t < NT; t++) {
        if (t + 1 < NT) { CP_WAIT(1); } else { CP_WAIT(0); }
        __syncthreads();
        if (t + 2 < NT) { g.load_stageP(A, Bt, m0, n0, K, (t + 2) << 6, (t + 2) % NSTAGE); CP_COMMIT(); }
        g.chunk_mma(t % NSTAGE, acc);
    }

#pragma unroll
    for (int i = 0; i < 4; i++)
#pragma unroll
        for (int half = 0; half < 2; half++) {
            const int gm = m0 + g.mW + i * 16 + g.grp + half * 8;
            __half* crow = C + (size_t)gm * HIDDEN;
#pragma unroll
            for (int j = 0; j < 4; j++) {
                const int gn = n0 + g.nW + j * 8 + g.t4 * 2;
                const float a0 = fmaxf(acc[i][j][half * 2 + 0] + bias[gn], 0.0f);
                const float a1 = fmaxf(acc[i][j][half * 2 + 1] + bias[gn + 1], 0.0f);
                *reinterpret_cast<__half2*>(crow + gn) = __floats2half2_rn(a0, a1);
            }
        }
}

// ---------------- merged stage 2 + 3a ----------------
// z=0: Hp = ReLU(concat(Hv|ppf) @ Wtf^T + b_pf), K=576, N=512 (4 n-tiles)
// z=1: out_s = Hs @ Wt2^T, K=512, N=1001 (8 n-tiles)
// z=2: out_o = Ho @ Wt2^T
__global__ void __launch_bounds__(256, 2)
gemm_mix(const __half* __restrict__ Hv, const __half* __restrict__ Hs,
         const __half* __restrict__ Ho, const __half* __restrict__ ppfh,
         const __half* __restrict__ Wtf, const __half* __restrict__ Wt2,
         const float* __restrict__ bpf,
         __half* __restrict__ Hp, float* __restrict__ out_s, float* __restrict__ out_o)
{
    const int z = blockIdx.z;
    const bool isPF = (z == 0);
    if (isPF && blockIdx.x >= 4) return;

    extern __shared__ __align__(16) char smem[];
    GemmCore g; g.init(smem_u32(smem));

    const __half* A  = isPF ? Hv : (z == 1) ? Hs : Ho;
    const __half* Bt = isPF ? Wtf : Wt2;
    const int K = isPF ? (HIDDEN + PPF_DIM) : HIDDEN;
    const int NT = K >> 6;                        // 9 or 8

    const int m0 = blockIdx.y * 128, n0 = blockIdx.x * 128;

    float acc[4][4][4];
    ACC_INIT(acc);

    g.load_stage(A, ppfh, Bt, m0, n0, K, 0, 0); CP_COMMIT();
    g.load_stage(A, ppfh, Bt, m0, n0, K, 64, 1); CP_COMMIT();
    for (int t = 0; t < NT; t++) {
        if (t + 1 < NT) { CP_WAIT(1); } else { CP_WAIT(0); }
        __syncthreads();
        if (t + 2 < NT) { g.load_stage(A, ppfh, Bt, m0, n0, K, (t + 2) << 6, (t + 2) % NSTAGE); CP_COMMIT(); }
        g.chunk_mma(t % NSTAGE, acc);
    }

#pragma unroll
    for (int i = 0; i < 4; i++)
#pragma unroll
        for (int half = 0; half < 2; half++) {
            const int gm = m0 + g.mW + i * 16 + g.grp + half * 8;
#pragma unroll
            for (int j = 0; j < 4; j++) {
                const int gn = n0 + g.nW + j * 8 + g.t4 * 2;
                const float v0 = acc[i][j][half * 2 + 0];
                const float v1 = acc[i][j][half * 2 + 1];
                if (isPF) {
                    __half* crow = Hp + (size_t)gm * HIDDEN;
                    const float a0 = fmaxf(v0 + bpf[gn], 0.0f);
                    const float a1 = fmaxf(v1 + bpf[gn + 1], 0.0f);
                    *reinterpret_cast<__half2*>(crow + gn) = __floats2half2_rn(a0, a1);
                } else {
                    float* crow = ((z == 1) ? out_s : out_o) + (size_t)gm * OBJ_NUM;
                    if (gn < OBJ_NUM)     crow[gn]     = v0;
                    if (gn + 1 < OBJ_NUM) crow[gn + 1] = v1;
                }
            }
        }
}

// ---------------- stage 3b: predicate scores + so2p gather ----------------
__global__ void __launch_bounds__(256, 2)
gemm_pred(const __half* __restrict__ Hp, const __half* __restrict__ Wtp,
          float* __restrict__ out_p,
          const int* __restrict__ gts, const int* __restrict__ gto,
          const float* __restrict__ so2p, const float* __restrict__ sof)
{
    extern __shared__ __align__(16) char smem[];
    GemmCore g; g.init(smem_u32(smem));

    const int m0 = blockIdx.y * 128, n0 = blockIdx.x * 128;
    const int K = HIDDEN, NT = K >> 6;

    float acc[4][4][4];
    ACC_INIT(acc);

    g.load_stageP(Hp, Wtp, m0, n0, K, 0, 0); CP_COMMIT();
    g.load_stageP(Hp, Wtp, m0, n0, K, 64, 1); CP_COMMIT();
    for (int t = 0; t < NT; t++) {
        if (t + 1 < NT) { CP_WAIT(1); } else { CP_WAIT(0); }
        __syncthreads();
        if (t + 2 < NT) { g.load_stageP(Hp, Wtp, m0, n0, K, (t + 2) << 6, (t + 2) % NSTAGE); CP_COMMIT(); }
        g.chunk_mma(t % NSTAGE, acc);
    }

    const float ef = expf(sof[0]);
#pragma unroll
    for (int i = 0; i < 4; i++)
#pragma unroll
        for (int half = 0; half < 2; half++) {
            const int gm = m0 + g.mW + i * 16 + g.grp + half * 8;
            const size_t sob = ((size_t)gts[gm] * OBJ_NUM + (size_t)gto[gm]) * (size_t)PRED_NUM;
            float* crow = out_p + (size_t)gm * PRED_NUM;
#pragma unroll
            for (int j = 0; j < 4; j++) {
                const int gn = n0 + g.nW + j * 8 + g.t4 * 2;
                const float v0 = acc[i][j][half * 2 + 0];
                const float v1 = acc[i][j][half * 2 + 1];
                if (gn < PRED_NUM)     crow[gn]     = v0 + so2p[sob + gn] * ef;
                if (gn + 1 < PRED_NUM) crow[gn + 1] = v1 + so2p[sob + gn + 1] * ef;
            }
        }
}

// ---------------- host ----------------
extern "C" void kernel_launch(void* const* d_in, const int* in_sizes, int n_in,
                              void* d_out, int out_size)
{
    const float* inp_sf  = (const float*)d_in[0];
    const float* inp_of  = (const float*)d_in[1];
    const float* inp_ppf = (const float*)d_in[2];
    const float* inp_pvf = (const float*)d_in[3];
    const int*   gt_s    = (const int*)d_in[4];
    const int*   gt_o    = (const int*)d_in[5];
    const float* W_obj1  = (const float*)d_in[6];
    const float* b_obj1  = (const float*)d_in[7];
    const float* W_obj2  = (const float*)d_in[8];
    const float* W_pvf   = (const float*)d_in[9];
    const float* b_pvf   = (const float*)d_in[10];
    const float* W_pf    = (const float*)d_in[11];
    const float* b_pf    = (const float*)d_in[12];
    const float* W_pred  = (const float*)d_in[13];
    const float* so2p    = (const float*)d_in[14];
    const float* sof     = (const float*)d_in[15];

    float* out   = (float*)d_out;
    float* out_s = out;
    float* out_o = out + (size_t)BQ * OBJ_NUM;
    float* out_p = out + (size_t)2 * BQ * OBJ_NUM;

    __half *sfh, *ofh, *pvfh, *ppfh, *Hs, *Ho, *Hv, *Hp, *Wt1, *Wtv, *Wtf, *Wt2, *Wtp;
    cudaGetSymbolAddress((void**)&sfh,  g_sfh);
    cudaGetSymbolAddress((void**)&ofh,  g_ofh);
    cudaGetSymbolAddress((void**)&pvfh, g_pvfh);
    cudaGetSymbolAddress((void**)&ppfh, g_ppfh);
    cudaGetSymbolAddress((void**)&Hs,  g_Hs);
    cudaGetSymbolAddress((void**)&Ho,  g_Ho);
    cudaGetSymbolAddress((void**)&Hv,  g_Hv);
    cudaGetSymbolAddress((void**)&Hp,  g_Hp);
    cudaGetSymbolAddress((void**)&Wt1, g_Wt1);
    cudaGetSymbolAddress((void**)&Wtv, g_Wtv);
    cudaGetSymbolAddress((void**)&Wtf, g_Wtf);
    cudaGetSymbolAddress((void**)&Wt2, g_Wt2);
    cudaGetSymbolAddress((void**)&Wtp, g_Wtp);

    cudaFuncSetAttribute(gemm_s1,   cudaFuncAttributeMaxDynamicSharedMemorySize, SMEM_BYTES);
    cudaFuncSetAttribute(gemm_mix,  cudaFuncAttributeMaxDynamicSharedMemorySize, SMEM_BYTES);
    cudaFuncSetAttribute(gemm_pred, cudaFuncAttributeMaxDynamicSharedMemorySize, SMEM_BYTES);

    // single fused prep launch (4 conversions + 5 transpose/pad/convert)
    prep<<<dim3(512, 1, 9), 256>>>(inp_sf, inp_of, inp_pvf, inp_ppf,
                                   sfh, ofh, pvfh, ppfh,
                                   W_obj1, W_pvf, W_pf, W_obj2, W_pred,
                                   Wt1, Wtv, Wtf, Wt2, Wtp);

    const dim3 blk(256);

    // stage 1: sf/of/pvf fused over z (K=1024, N=512)
    gemm_s1<<<dim3(HIDDEN / 128, BQ / 128, 3), blk, SMEM_BYTES>>>(
        sfh, ofh, pvfh, Wt1, Wtv, b_obj1, b_pvf, Hs, Ho, Hv);

    // merged stage 2 + 3a: z=0 pf_emb (4 n-tiles), z=1/2 s/o scores (8 n-tiles)
    gemm_mix<<<dim3(OBJ_PAD / 128, BQ / 128, 3), blk, SMEM_BYTES>>>(
        Hv, Hs, Ho, ppfh, Wtf, Wt2, b_pf, Hp, out_s, out_o);

    // stage 3b: predicate scores + so2p gather (K=512, N=132 padded 256)
    gemm_pred<<<dim3(PRED_PAD / 128, BQ / 128, 1), blk, SMEM_BYTES>>>(
        Hp, Wtp, out_p, gt_s, gt_o, so2p, sof);
}

// round 10
// speedup vs baseline: 1.2317x; 1.0190x over previous
#include <cuda_runtime.h>
#include <cuda_fp16.h>
#include <math.h>
#include <stdint.h>

#define BQ        16384
#define OBJ_FEAT  1024
#define PVF_DIM   1024
#define PPF_DIM   64
#define HIDDEN    512
#define OBJ_NUM   1001
#define PRED_NUM  132

#define OBJ_PAD   1024
#define PRED_PAD  256
#define MBLK      (BQ / 128)                    // 128 m-blocks

// ---------------- scratch (__device__ globals; allocation-free rule) --------
__device__ __half g_sfh[(size_t)BQ * OBJ_FEAT];
__device__ __half g_ofh[(size_t)BQ * OBJ_FEAT];
__device__ __half g_pvfh[(size_t)BQ * PVF_DIM];
__device__ __half g_ppfh[(size_t)BQ * PPF_DIM];
__device__ __half g_Hs[(size_t)BQ * HIDDEN];
__device__ __half g_Ho[(size_t)BQ * HIDDEN];
__device__ __half g_Hv[(size_t)BQ * HIDDEN];
__device__ __half g_Hp[(size_t)BQ * HIDDEN];
__device__ __half g_Wt1[(size_t)HIDDEN * OBJ_FEAT];            // [512][1024]
__device__ __half g_Wtv[(size_t)HIDDEN * PVF_DIM];             // [512][1024]
__device__ __half g_Wtf[(size_t)HIDDEN * (HIDDEN + PPF_DIM)];  // [512][576]
__device__ __half g_Wt2[(size_t)OBJ_PAD * HIDDEN];             // [1024][512]
__device__ __half g_Wtp[(size_t)PRED_PAD * HIDDEN];            // [256][512]

// per-row-block completion counters (cleared by prep each run)
__device__ int g_cnt_s1[3 * MBLK];              // s1 z-slice, 4 n-tiles each
__device__ int g_cnt_pf[MBLK];                  // pf, 4 n-tiles each

// ---------------- PTX helpers ----------------
__device__ __forceinline__ uint32_t smem_u32(const void* p) {
    uint32_t a;
    asm("{ .reg .u64 t; cvta.to.shared.u64 t, %1; cvt.u32.u64 %0, t; }" : "=r"(a) : "l"(p));
    return a;
}
__device__ __forceinline__ void mma_f16(float* c, const uint32_t* a, const uint32_t* b) {
    asm volatile(
        "mma.sync.aligned.m16n8k16.row.col.f32.f16.f16.f32 "
        "{%0,%1,%2,%3}, {%4,%5,%6,%7}, {%8,%9}, {%0,%1,%2,%3};"
        : "+f"(c[0]), "+f"(c[1]), "+f"(c[2]), "+f"(c[3])
        : "r"(a[0]), "r"(a[1]), "r"(a[2]), "r"(a[3]), "r"(b[0]), "r"(b[1]));
}
#define LDSM_X4(r0, r1, r2, r3, addr) \
    asm volatile("ldmatrix.sync.aligned.m8n8.x4.shared.b16 {%0,%1,%2,%3}, [%4];" \
        : "=r"(r0), "=r"(r1), "=r"(r2), "=r"(r3) : "r"(addr))
__device__ __forceinline__ void cp16cg(uint32_t dst, const void* src) {
    asm volatile("cp.async.cg.shared.global [%0], [%1], 16;" :: "r"(dst), "l"(src));
}
__device__ __forceinline__ void cp16ca(uint32_t dst, const void* src) {
    asm volatile("cp.async.ca.shared.global [%0], [%1], 16;" :: "r"(dst), "l"(src));
}
#define CP_COMMIT() asm volatile("cp.async.commit_group;" ::: "memory")
#define CP_WAIT(n)  asm volatile("cp.async.wait_group %0;" :: "n"(n) : "memory")

// producer handoff: all stores visible, then one count
__device__ __forceinline__ void signal_done(int* c) {
    __threadfence();
    __syncthreads();
    if (threadIdx.x == 0) atomicAdd(c, 1);
}
// consumer: spin until target n-tiles done
__device__ __forceinline__ void wait_cnt(int* c, int target) {
    if (threadIdx.x == 0) {
        while (atomicAdd(c, 0) < target) __nanosleep(64);
        __threadfence();
    }
    __syncthreads();
}

// ---------------- smem layout: 3 stages, A/B tiles [128 rows][64+8 halves] --
#define ROWB      144                           // 128B data + 16B pad
#define T_STAGE   (128 * ROWB)                  // 18432 B
#define STAGE_B   (2 * T_STAGE)                 // 36864 B (A then B)
#define NSTAGE    3
#define SMEM_BYTES (NSTAGE * STAGE_B)           // 110592 B

// ---------------- fused prep: flag clear + conversions + transposes --------
__global__ void prep(const float* __restrict__ sf, const float* __restrict__ of,
                     const float* __restrict__ pvf, const float* __restrict__ ppf,
                     __half* __restrict__ sfh, __half* __restrict__ ofh,
                     __half* __restrict__ pvfh, __half* __restrict__ ppfh,
                     const float* __restrict__ W1, const float* __restrict__ Wv,
                     const float* __restrict__ Wf, const float* __restrict__ W2,
                     const float* __restrict__ Wp,
                     __half* __restrict__ Wt1, __half* __restrict__ Wtv,
                     __half* __restrict__ Wtf, __half* __restrict__ Wt2,
                     __half* __restrict__ Wtp)
{
    const int z = blockIdx.z;
    if (z == 0 && blockIdx.x == 0) {            // reset flags for this replay
        for (int i = threadIdx.x; i < 3 * MBLK; i += blockDim.x) g_cnt_s1[i] = 0;
        for (int i = threadIdx.x; i < MBLK; i += blockDim.x) g_cnt_pf[i] = 0;
    }
    if (z < 4) {
        const float* in = (z == 0) ? sf : (z == 1) ? of : (z == 2) ? pvf : ppf;
        __half* out = (z == 0) ? sfh : (z == 1) ? ofh : (z == 2) ? pvfh : ppfh;
        const int n8 = (z == 3) ? (BQ * PPF_DIM / 8) : (BQ * OBJ_FEAT / 8);
        for (int i = blockIdx.x * blockDim.x + threadIdx.x; i < n8;
             i += gridDim.x * blockDim.x) {
            const float4 a = *reinterpret_cast<const float4*>(in + (size_t)i * 8);
            const float4 b = *reinterpret_cast<const float4*>(in + (size_t)i * 8 + 4);
            __half2 h[4];
            h[0] = __floats2half2_rn(a.x, a.y);
            h[1] = __floats2half2_rn(a.z, a.w);
            h[2] = __floats2half2_rn(b.x, b.y);
            h[3] = __floats2half2_rn(b.z, b.w);
            *reinterpret_cast<uint4*>(out + (size_t)i * 8) = *reinterpret_cast<uint4*>(h);
        }
    } else {
        const float* W; __half* Wt; int K, N, Npad;
        switch (z) {
            case 4: W = W1; Wt = Wt1; K = OBJ_FEAT; N = HIDDEN; Npad = HIDDEN; break;
            case 5: W = Wv; Wt = Wtv; K = PVF_DIM;  N = HIDDEN; Npad = HIDDEN; break;
            case 6: W = Wf; Wt = Wtf; K = HIDDEN + PPF_DIM; N = HIDDEN; Npad = HIDDEN; break;
            case 7: W = W2; Wt = Wt2; K = HIDDEN; N = OBJ_NUM;  Npad = OBJ_PAD; break;
            default: W = Wp; Wt = Wtp; K = HIDDEN; N = PRED_NUM; Npad = PRED_PAD; break;
        }
        __shared__ float t[32][33];
        const int tx5 = threadIdx.x & 31, ty3 = threadIdx.x >> 5;  // (32, 8)
        const int ntx = Npad / 32, nty = (K + 31) / 32;
        for (int tile = blockIdx.x; tile < ntx * nty; tile += gridDim.x) {
            const int bx = (tile % ntx) * 32;   // n
            const int by = (tile / ntx) * 32;   // k
#pragma unroll
            for (int j = 0; j < 32; j += 8) {
                const int y = by + ty3 + j, x = bx + tx5;
                t[ty3 + j][tx5] = (x < N && y < K) ? W[(size_t)y * N + x] : 0.0f;
            }
            __syncthreads();
#pragma unroll
            for (int j = 0; j < 32; j += 8) {
                const int row = bx + ty3 + j, col = by + tx5;
                if (row < Npad && col < K)
                    Wt[(size_t)row * K + col] = __float2half(t[tx5][ty3 + j]);
            }
            __syncthreads();
        }
    }
}

// ================= round-6 champion GEMM core (unchanged) ==================
struct GemmCore {
    uint32_t sbase;
    int tid, lane, grp, t4, mW, nW;
    uint32_t offA, offB;
    int ldRow, ldQ0;

    __device__ __forceinline__ void init(uint32_t sb) {
        sbase = sb;
        tid = threadIdx.x;
        const int wid = tid >> 5;
        lane = tid & 31;
        grp = lane >> 2; t4 = lane & 3;
        const int wy = wid >> 2, wx = wid & 3;     // warp grid 2x4
        mW = wy * 64; nW = wx * 32;
        offA = (uint32_t)(lane & 15) * ROWB + (uint32_t)(lane >> 4) * 16;
        const uint32_t bR = (uint32_t)((lane & 7) + ((lane >> 4) & 1) * 8);
        offB = bR * ROWB + (uint32_t)((lane >> 3) & 1) * 16;
        ldRow = tid >> 1;
        ldQ0 = (tid & 1) * 4;
    }

    // concat-style A loader (row stride HIDDEN; A2 branch only if k >= HIDDEN)
    __device__ __forceinline__ void load_stage(const __half* __restrict__ A,
                                               const __half* __restrict__ A2,
                                               const __half* __restrict__ Bt,
                                               int m0, int n0, int K,
                                               int kc, int s) const {
        const uint32_t abase = sbase + s * STAGE_B;
        const uint32_t bbase = abase + T_STAGE;
#pragma unroll
        for (int i = 0; i < 4; i++) {
            const int q = ldQ0 + i;
            const int k = kc + q * 8;
            const uint32_t dst = abase + (uint32_t)ldRow * ROWB + (uint32_t)q * 16;
            const __half* src = (k < HIDDEN)
                ? (A  + (size_t)(m0 + ldRow) * HIDDEN + k)
                : (A2 + (size_t)(m0 + ldRow) * PPF_DIM + (k - HIDDEN));
            cp16cg(dst, src);
        }
#pragma unroll
        for (int i = 0; i < 4; i++) {
            const int q = ldQ0 + i;
            const uint32_t dst = bbase + (uint32_t)ldRow * ROWB + (uint32_t)q * 16;
            cp16ca(dst, Bt + (size_t)(n0 + ldRow) * K + kc + q * 8);
        }
    }

    // plain A (row stride == K)
    __device__ __forceinline__ void load_stageP(const __half* __restrict__ A,
                                                const __half* __restrict__ Bt,
                                                int m0, int n0, int K,
                                                int kc, int s) const {
        const uint32_t abase = sbase + s * STAGE_B;
        const uint32_t bbase = abase + T_STAGE;
#pragma unroll
        for (int i = 0; i < 4; i++) {
            const int q = ldQ0 + i;
            const uint32_t dst = abase + (uint32_t)ldRow * ROWB + (uint32_t)q * 16;
            cp16cg(dst, A + (size_t)(m0 + ldRow) * K + kc + q * 8);
        }
#pragma unroll
        for (int i = 0; i < 4; i++) {
            const int q = ldQ0 + i;
            const uint32_t dst = bbase + (uint32_t)ldRow * ROWB + (uint32_t)q * 16;
            cp16ca(dst, Bt + (size_t)(n0 + ldRow) * K + kc + q * 8);
        }
    }

    __device__ __forceinline__ void chunk_mma(int s, float acc[4][4][4]) const {
        const uint32_t abase = sbase + s * STAGE_B;
        const uint32_t bbase = abase + T_STAGE;
#pragma unroll
        for (int ks = 0; ks < 4; ks++) {
            const uint32_t kb = (uint32_t)ks * 32;
            uint32_t af[4][4], bf[4][2];
#pragma unroll
            for (int i = 0; i < 4; i++) {
                const uint32_t ad = abase + (uint32_t)(mW + i * 16) * ROWB + kb + offA;
                LDSM_X4(af[i][0], af[i][1], af[i][2], af[i][3], ad);
            }
#pragma unroll
            for (int jp = 0; jp < 2; jp++) {
                const uint32_t bd = bbase + (uint32_t)(nW + jp * 16) * ROWB + kb + offB;
                LDSM_X4(bf[2 * jp][0], bf[2 * jp][1], bf[2 * jp + 1][0], bf[2 * jp + 1][1], bd);
            }
#pragma unroll
            for (int i = 0; i < 4; i++)
#pragma unroll
                for (int j = 0; j < 4; j++)
                    mma_f16(acc[i][j], af[i], bf[j]);
        }
    }
};

#define ACC_INIT(acc) \
    _Pragma("unroll") for (int i = 0; i < 4; i++) \
    _Pragma("unroll") for (int j = 0; j < 4; j++) \
    _Pragma("unroll") for (int r = 0; r < 4; r++) acc[i][j][r] = 0.0f;

__device__ __forceinline__ void kloopP(const GemmCore& g, const __half* A,
                                       const __half* Bt, int m0, int n0, int K,
                                       float acc[4][4][4]) {
    const int NT = K >> 6;
    g.load_stageP(A, Bt, m0, n0, K, 0, 0); CP_COMMIT();
    g.load_stageP(A, Bt, m0, n0, K, 64, 1); CP_COMMIT();
    for (int t = 0; t < NT; t++) {
        if (t + 1 < NT) { CP_WAIT(1); } else { CP_WAIT(0); }
        __syncthreads();
        if (t + 2 < NT) { g.load_stageP(A, Bt, m0, n0, K, (t + 2) << 6, (t + 2) % NSTAGE); CP_COMMIT(); }
        g.chunk_mma(t % NSTAGE, acc);
    }
}
__device__ __forceinline__ void kloopC(const GemmCore& g, const __half* A,
                                       const __half* A2, const __half* Bt,
                                       int m0, int n0, int K, float acc[4][4][4]) {
    const int NT = K >> 6;
    g.load_stage(A, A2, Bt, m0, n0, K, 0, 0); CP_COMMIT();
    g.load_stage(A, A2, Bt, m0, n0, K, 64, 1); CP_COMMIT();
    for (int t = 0; t < NT; t++) {
        if (t + 1 < NT) { CP_WAIT(1); } else { CP_WAIT(0); }
        __syncthreads();
        if (t + 2 < NT) { g.load_stage(A, A2, Bt, m0, n0, K, (t + 2) << 6, (t + 2) % NSTAGE); CP_COMMIT(); }
        g.chunk_mma(t % NSTAGE, acc);
    }
}

// ---------------- mega-kernel: all 6 GEMMs, producers-first dispatch -------
// idx [0,1536)    : s1  (z = idx/512)   C = Hs/Ho/Hv      (bias+ReLU, half)
// idx [1536,2048) : pf  (waits Hv)      C = Hp            (bias+ReLU, half)
// idx [2048,4096) : s/o (waits Hs/Ho)   C = out_s/out_o   (plain, float)
// idx [4096,4352) : pred (waits Hp)     C = out_p         (so2p gather)
__global__ void __launch_bounds__(256, 2)
gemm_all(const float* __restrict__ b_obj1, const float* __restrict__ b_pvf,
         const float* __restrict__ b_pf,
         float* __restrict__ out_s, float* __restrict__ out_o,
         float* __restrict__ out_p,
         const int* __restrict__ gts, const int* __restrict__ gto,
         const float* __restrict__ so2p, const float* __restrict__ sof)
{
    extern __shared__ __align__(16) char smem[];
    GemmCore g; g.init(smem_u32(smem));
    const int idx = blockIdx.x;

    float acc[4][4][4];
    ACC_INIT(acc);

    if (idx < 1536) {                       // ---- stage 1 ----
        const int z = idx >> 9, rem = idx & 511;
        const int n0 = (rem & 3) * 128, mb = rem >> 2, m0 = mb * 128;
        const __half* A  = (z == 0) ? g_sfh : (z == 1) ? g_ofh : g_pvfh;
        const __half* Bt = (z == 2) ? g_Wtv : g_Wt1;
        const float* bias = (z == 2) ? b_pvf : b_obj1;
        __half* C = (z == 0) ? g_Hs : (z == 1) ? g_Ho : g_Hv;

        kloopP(g, A, Bt, m0, n0, OBJ_FEAT, acc);

#pragma unroll
        for (int i = 0; i < 4; i++)
#pragma unroll
            for (int half = 0; half < 2; half++) {
                const int gm = m0 + g.mW + i * 16 + g.grp + half * 8;
                __half* crow = C + (size_t)gm * HIDDEN;
#pragma unroll
                for (int j = 0; j < 4; j++) {
                    const int gn = n0 + g.nW + j * 8 + g.t4 * 2;
                    const float a0 = fmaxf(acc[i][j][half * 2 + 0] + bias[gn], 0.0f);
                    const float a1 = fmaxf(acc[i][j][half * 2 + 1] + bias[gn + 1], 0.0f);
                    *reinterpret_cast<__half2*>(crow + gn) = __floats2half2_rn(a0, a1);
                }
            }
        signal_done(&g_cnt_s1[z * MBLK + mb]);

    } else if (idx < 2048) {                // ---- pf_emb ----
        const int rem = idx - 1536;
        const int n0 = (rem & 3) * 128, mb = rem >> 2, m0 = mb * 128;
        wait_cnt(&g_cnt_s1[2 * MBLK + mb], 4);

        kloopC(g, g_Hv, g_ppfh, g_Wtf, m0, n0, HIDDEN + PPF_DIM, acc);

#pragma unroll
        for (int i = 0; i < 4; i++)
#pragma unroll
            for (int half = 0; half < 2; half++) {
                const int gm = m0 + g.mW + i * 16 + g.grp + half * 8;
                __half* crow = g_Hp + (size_t)gm * HIDDEN;
#pragma unroll
                for (int j = 0; j < 4; j++) {
                    const int gn = n0 + g.nW + j * 8 + g.t4 * 2;
                    const float a0 = fmaxf(acc[i][j][half * 2 + 0] + b_pf[gn], 0.0f);
                    const float a1 = fmaxf(acc[i][j][half * 2 + 1] + b_pf[gn + 1], 0.0f);
                    *reinterpret_cast<__half2*>(crow + gn) = __floats2half2_rn(a0, a1);
                }
            }
        signal_done(&g_cnt_pf[mb]);

    } else if (idx < 4096) {                // ---- s / o scores ----
        const int rem = idx - 2048;
        const int z = rem >> 10, rem2 = rem & 1023;
        const int n0 = (rem2 & 7) * 128, mb = rem2 >> 3, m0 = mb * 128;
        wait_cnt(&g_cnt_s1[z * MBLK + mb], 4);

        const __half* A = z ? g_Ho : g_Hs;
        float* C = z ? out_o : out_s;

        kloopC(g, A, g_ppfh, g_Wt2, m0, n0, HIDDEN, acc);

#pragma unroll
        for (int i = 0; i < 4; i++)
#pragma unroll
            for (int half = 0; half < 2; half++) {
                const int gm = m0 + g.mW + i * 16 + g.grp + half * 8;
                float* crow = C + (size_t)gm * OBJ_NUM;
#pragma unroll
                for (int j = 0; j < 4; j++) {
                    const int gn = n0 + g.nW + j * 8 + g.t4 * 2;
                    if (gn < OBJ_NUM)     crow[gn]     = acc[i][j][half * 2 + 0];
                    if (gn + 1 < OBJ_NUM) crow[gn + 1] = acc[i][j][half * 2 + 1];
                }
            }

    } else {                                // ---- predicate + so2p ----
        const int rem = idx - 4096;
        const int n0 = (rem & 1) * 128, mb = rem >> 1, m0 = mb * 128;
        wait_cnt(&g_cnt_pf[mb], 4);

        kloopC(g, g_Hp, g_ppfh, g_Wtp, m0, n0, HIDDEN, acc);

        const float ef = expf(sof[0]);
#pragma unroll
        for (int i = 0; i < 4; i++)
#pragma unroll
            for (int half = 0; half < 2; half++) {
                const int gm = m0 + g.mW + i * 16 + g.grp + half * 8;
                const size_t sob = ((size_t)gts[gm] * OBJ_NUM + (size_t)gto[gm]) * (size_t)PRED_NUM;
                float* crow = out_p + (size_t)gm * PRED_NUM;
#pragma unroll
                for (int j = 0; j < 4; j++) {
                    const int gn = n0 + g.nW + j * 8 + g.t4 * 2;
                    const float v0 = acc[i][j][half * 2 + 0];
                    const float v1 = acc[i][j][half * 2 + 1];
                    if (gn < PRED_NUM)     crow[gn]     = v0 + so2p[sob + gn] * ef;
                    if (gn + 1 < PRED_NUM) crow[gn + 1] = v1 + so2p[sob + gn + 1] * ef;
                }
            }
    }
}

// ---------------- host ----------------
extern "C" void kernel_launch(void* const* d_in, const int* in_sizes, int n_in,
                              void* d_out, int out_size)
{
    const float* inp_sf  = (const float*)d_in[0];
    const float* inp_of  = (const float*)d_in[1];
    const float* inp_ppf = (const float*)d_in[2];
    const float* inp_pvf = (const float*)d_in[3];
    const int*   gt_s    = (const int*)d_in[4];
    const int*   gt_o    = (const int*)d_in[5];
    const float* W_obj1  = (const float*)d_in[6];
    const float* b_obj1  = (const float*)d_in[7];
    const float* W_obj2  = (const float*)d_in[8];
    const float* W_pvf   = (const float*)d_in[9];
    const float* b_pvf   = (const float*)d_in[10];
    const float* W_pf    = (const float*)d_in[11];
    const float* b_pf    = (const float*)d_in[12];
    const float* W_pred  = (const float*)d_in[13];
    const float* so2p    = (const float*)d_in[14];
    const float* sof     = (const float*)d_in[15];

    float* out   = (float*)d_out;
    float* out_s = out;
    float* out_o = out + (size_t)BQ * OBJ_NUM;
    float* out_p = out + (size_t)2 * BQ * OBJ_NUM;

    __half *sfh, *ofh, *pvfh, *ppfh, *Wt1, *Wtv, *Wtf, *Wt2, *Wtp;
    cudaGetSymbolAddress((void**)&sfh,  g_sfh);
    cudaGetSymbolAddress((void**)&ofh,  g_ofh);
    cudaGetSymbolAddress((void**)&pvfh, g_pvfh);
    cudaGetSymbolAddress((void**)&ppfh, g_ppfh);
    cudaGetSymbolAddress((void**)&Wt1, g_Wt1);
    cudaGetSymbolAddress((void**)&Wtv, g_Wtv);
    cudaGetSymbolAddress((void**)&Wtf, g_Wtf);
    cudaGetSymbolAddress((void**)&Wt2, g_Wt2);
    cudaGetSymbolAddress((void**)&Wtp, g_Wtp);

    cudaFuncSetAttribute(gemm_all, cudaFuncAttributeMaxDynamicSharedMemorySize, SMEM_BYTES);

    // prep: flag clear + 4 conversions + 5 transpose/pad/convert
    prep<<<dim3(512, 1, 9), 256>>>(inp_sf, inp_of, inp_pvf, inp_ppf,
                                   sfh, ofh, pvfh, ppfh,
                                   W_obj1, W_pvf, W_pf, W_obj2, W_pred,
                                   Wt1, Wtv, Wtf, Wt2, Wtp);

    // all six GEMMs in one launch; row-block flags order the dependencies
    gemm_all<<<4352, 256, SMEM_BYTES>>>(b_obj1, b_pvf, b_pf,
                                        out_s, out_o, out_p,
                                        gt_s, gt_o, so2p, sof);
}